// round 1
// baseline (speedup 1.0000x reference)
#include <cuda_runtime.h>
#include <cuda_bf16.h>
#include <cstdint>

// Problem constants
// x: (128, 512, 14, 14) fp32 ; W: (20, 512) fp32
// T=8, n=16, B=3136, c=512, H=4, K=5, O=20, R=128
#define NT   128
#define CCH  512
#define HWS  196
#define TT   8
#define NN   16
#define HH   4
#define KK   5
#define OO   20
#define BB   3136   // NN * HWS

// scratch: softmax weights laid out [h][b][t][k]  (contiguous per-head slice)
__device__ float g_weights[(size_t)HH * BB * TT * KK];

// packed f32x2 fma (sm_103a): d = a*b + d on both 32-bit lanes
#define FMA2(accv, xv, wv) \
    asm("fma.rn.f32x2 %0, %1, %2, %0;" : "+l"(accv) : "l"(xv), "l"(wv))

// ---------------------------------------------------------------------------
// Kernel 1: logits (dot over c=512 with 20 W rows) + softmax over K=5 taps.
// Block = 128 threads: warp w = c-slice [w*128, w*128+128), lane = spatial PAIR.
// Each thread accumulates 20 packed-f32x2 logits for 2 adjacent spatial
// positions; cross-warp (c-slice) reduction via shared; warp 0 does softmax.
// grid.x = NT * 4  (4 blocks of 32 pairs cover the 98 pairs per image)
// Dynamic shared: Wsp splat (512*20 float2 = 81920B) + red (3*32*20 float2 = 15360B)
// ---------------------------------------------------------------------------
__global__ void __launch_bounds__(128)
weights_kernel(const float* __restrict__ x, const float* __restrict__ W)
{
    extern __shared__ float smem[];
    float2* Wsp = reinterpret_cast<float2*>(smem);            // [c][o] splatted
    float2* red = reinterpret_cast<float2*>(smem + 2 * CCH * OO); // [3][32][20]

    const int tid = threadIdx.x;

    // Load + splat W into shared: Wsp[c*20+o] = {W[o][c], W[o][c]}
    // Read coalesced over the flat W array.
    for (int i = tid; i < OO * CCH; i += 128) {
        const int o = i >> 9;       // i / 512
        const int c = i & (CCH - 1);
        const float v = W[i];
        Wsp[c * OO + o] = make_float2(v, v);
    }
    __syncthreads();

    const int nt    = blockIdx.x >> 2;
    const int pbase = (blockIdx.x & 3) * 32;
    const int cs    = tid >> 5;   // warp = c-slice
    const int lane  = tid & 31;
    const int p     = pbase + lane;          // spatial-pair index, valid if < 98
    const bool valid = (p < 98);

    unsigned long long acc[OO];
#pragma unroll
    for (int o = 0; o < OO; ++o) acc[o] = 0ull;

    if (valid) {
        const float* xrow = x + ((size_t)nt * CCH + (size_t)cs * 128) * HWS + 2 * p;
#pragma unroll 4
        for (int cc = 0; cc < 128; ++cc) {
            const unsigned long long xv =
                *reinterpret_cast<const unsigned long long*>(xrow + (size_t)cc * HWS);
            const float2* wr = Wsp + (cs * 128 + cc) * OO;
#pragma unroll
            for (int j = 0; j < 10; ++j) {
                const ulonglong2 wp =
                    *reinterpret_cast<const ulonglong2*>(wr + 2 * j); // 16B aligned
                FMA2(acc[2 * j],     xv, wp.x);
                FMA2(acc[2 * j + 1], xv, wp.y);
            }
        }
    }

    // cross-warp reduction: warps 1..3 dump partials, warp 0 sums
    if (cs > 0) {
        float2* dst = red + ((cs - 1) * 32 + lane) * OO;
#pragma unroll
        for (int o = 0; o < OO; ++o)
            dst[o] = *reinterpret_cast<float2*>(&acc[o]);
    }
    __syncthreads();

    if (cs == 0 && valid) {
        float l[2][OO];
#pragma unroll
        for (int o = 0; o < OO; ++o) {
            const float2 a = *reinterpret_cast<float2*>(&acc[o]);
            l[0][o] = a.x; l[1][o] = a.y;
        }
#pragma unroll
        for (int w = 0; w < 3; ++w) {
            const float2* s = red + (w * 32 + lane) * OO;
#pragma unroll
            for (int o = 0; o < OO; ++o) {
                const float2 a = s[o];
                l[0][o] += a.x; l[1][o] += a.y;
            }
        }

        const int t   = nt & (TT - 1);
        const int n_i = nt >> 3;
#pragma unroll
        for (int j = 0; j < 2; ++j) {
            const int b = n_i * HWS + 2 * p + j;
#pragma unroll
            for (int h = 0; h < HH; ++h) {
                float m = l[j][h * KK];
#pragma unroll
                for (int k = 1; k < KK; ++k) m = fmaxf(m, l[j][h * KK + k]);
                float e[KK], s = 0.f;
#pragma unroll
                for (int k = 0; k < KK; ++k) {
                    e[k] = __expf(l[j][h * KK + k] - m);
                    s += e[k];
                }
                const float inv = 1.f / s;
                float* dst = g_weights + (((size_t)h * BB + b) * TT + t) * KK;
#pragma unroll
                for (int k = 0; k < KK; ++k) dst[k] = e[k] * inv;
            }
        }
    }
}

// ---------------------------------------------------------------------------
// Kernel 2: causal 5-tap combine.
// grid = (n_i : 16, ct : 32) ; block = 224 threads (196 active = spatial pos).
// Each block: one image, one 16-channel tile (single head h = ct/8).
// Per-head weight slice (196 b * 40 floats) staged in shared, hoisted to regs.
// x loads / out stores are fully coalesced over spatial.
// ---------------------------------------------------------------------------
__global__ void __launch_bounds__(224)
combine_kernel(const float* __restrict__ x, float* __restrict__ out)
{
    __shared__ float wsh[HWS][41];   // 40 weights per sp, pad->41 (conflict-free)

    const int n_i = blockIdx.x;
    const int ct  = blockIdx.y;           // channel tile of 16
    const int h   = ct >> 3;              // (ct*16)/128

    const float* wsrc = g_weights + ((size_t)h * BB + (size_t)n_i * HWS) * (TT * KK);
    for (int i = threadIdx.x; i < HWS * TT * KK; i += 224)
        wsh[i / 40][i % 40] = wsrc[i];
    __syncthreads();

    const int sp = threadIdx.x;
    if (sp < HWS) {
        float wt[TT][KK];
#pragma unroll
        for (int t = 0; t < TT; ++t)
#pragma unroll
            for (int k = 0; k < KK; ++k)
                wt[t][k] = wsh[sp][t * KK + k];

        const size_t tstride = (size_t)CCH * HWS;           // between nt slices
        const size_t base = ((size_t)n_i * TT * CCH + (size_t)ct * 16) * HWS + sp;

        for (int c = 0; c < 16; ++c) {
            const float* xp = x   + base + (size_t)c * HWS;
            float*       op = out + base + (size_t)c * HWS;
            float xv[TT];
#pragma unroll
            for (int t = 0; t < TT; ++t) xv[t] = xp[(size_t)t * tstride];
#pragma unroll
            for (int t = 0; t < TT; ++t) {
                float s = 0.f;
#pragma unroll
                for (int k = 0; k < KK; ++k) {
                    const int src = t + k - 4;               // causal: zero-pad left
                    if (src >= 0) s = fmaf(wt[t][k], xv[src], s);
                }
                op[(size_t)t * tstride] = s;
            }
        }
    }
}

// ---------------------------------------------------------------------------
extern "C" void kernel_launch(void* const* d_in, const int* in_sizes, int n_in,
                              void* d_out, int out_size)
{
    const float* x = (const float*)d_in[0];
    const float* W = (const float*)d_in[1];
    float* out = (float*)d_out;

    const int smem1 = 2 * CCH * OO * 4 + 3 * 32 * OO * 8;   // 81920 + 15360 = 97280
    cudaFuncSetAttribute(weights_kernel,
                         cudaFuncAttributeMaxDynamicSharedMemorySize, smem1);

    weights_kernel<<<NT * 4, 128, smem1>>>(x, W);
    combine_kernel<<<dim3(NN, 32), 224>>>(x, out);
}

// round 3
// speedup vs baseline: 1.0956x; 1.0956x over previous
#include <cuda_runtime.h>
#include <cuda_bf16.h>
#include <cstdint>

// x: (128, 512, 14, 14) fp32 ; W: (20, 512) fp32
// T=8, n=16, B=3136, c=512, H=4, K=5, O=20
#define NT   128
#define CCH  512
#define HWS  196
#define TT   8
#define NN   16
#define HH   4
#define KK   5
#define OO   20
#define BB   3136   // NN * HWS

// scratch: softmax weights laid out [h][b][t][k] (contiguous per-(h,n_i) slice)
__device__ float g_weights[(size_t)HH * BB * TT * KK];

// packed f32x2 fma (sm_103a): d = a*b + d on both 32-bit lanes
#define FMA2(accv, xv, wv) \
    asm("fma.rn.f32x2 %0, %1, %2, %0;" : "+l"(accv) : "l"(xv), "l"(wv))

// ---------------------------------------------------------------------------
// Kernel 1: logits (dot over c=512 with 20 W rows) + softmax over K=5 taps.
// Block = 128 threads: warp = c-slice of 128 channels, lane = spatial PAIR
// (f32x2 packs 2 adjacent spatial positions). 8-deep explicit x prefetch for
// MLP. Cross-warp reduction via shared; warp 0 does softmax + store.
// grid.x = NT*4 (4 blocks of 32 pairs cover 98 pairs per image)
// ---------------------------------------------------------------------------
__global__ void __launch_bounds__(128)
weights_kernel(const float* __restrict__ x, const float* __restrict__ W)
{
    extern __shared__ float smem[];
    float2* Wsp = reinterpret_cast<float2*>(smem);                // [c][o] splat
    float2* red = reinterpret_cast<float2*>(smem + 2 * CCH * OO); // [3][32][20]

    const int tid = threadIdx.x;

    // Load + splat W into shared: Wsp[c*20+o] = {W[o][c], W[o][c]}
    for (int i = tid; i < OO * CCH; i += 128) {
        const int o = i >> 9;
        const int c = i & (CCH - 1);
        const float v = W[i];
        Wsp[c * OO + o] = make_float2(v, v);
    }
    __syncthreads();

    const int nt    = blockIdx.x >> 2;
    const int pbase = (blockIdx.x & 3) * 32;
    const int cs    = tid >> 5;   // warp = c-slice
    const int lane  = tid & 31;
    const int p     = pbase + lane;          // spatial-pair index
    const bool valid = (p < 98);

    unsigned long long acc[OO];
#pragma unroll
    for (int o = 0; o < OO; ++o) acc[o] = 0ull;

    if (valid) {
        const float* xrow = x + ((size_t)nt * CCH + (size_t)cs * 128) * HWS + 2 * p;
        for (int c0 = 0; c0 < 128; c0 += 8) {
            // front-batch 8 independent global loads (MLP=8)
            unsigned long long xv8[8];
#pragma unroll
            for (int i = 0; i < 8; ++i)
                xv8[i] = *reinterpret_cast<const unsigned long long*>(
                             xrow + (size_t)(c0 + i) * HWS);
#pragma unroll
            for (int i = 0; i < 8; ++i) {
                const float2* wr = Wsp + (cs * 128 + c0 + i) * OO;
#pragma unroll
                for (int j = 0; j < 10; ++j) {
                    const ulonglong2 wp =
                        *reinterpret_cast<const ulonglong2*>(wr + 2 * j);
                    FMA2(acc[2 * j],     xv8[i], wp.x);
                    FMA2(acc[2 * j + 1], xv8[i], wp.y);
                }
            }
        }
    }

    // cross-warp reduction: warps 1..3 dump partials, warp 0 sums
    if (cs > 0) {
        float2* dst = red + ((cs - 1) * 32 + lane) * OO;
#pragma unroll
        for (int o = 0; o < OO; ++o)
            dst[o] = *reinterpret_cast<float2*>(&acc[o]);
    }
    __syncthreads();

    if (cs == 0 && valid) {
        float l[2][OO];
#pragma unroll
        for (int o = 0; o < OO; ++o) {
            const float2 a = *reinterpret_cast<float2*>(&acc[o]);
            l[0][o] = a.x; l[1][o] = a.y;
        }
#pragma unroll
        for (int w = 0; w < 3; ++w) {
            const float2* s = red + (w * 32 + lane) * OO;
#pragma unroll
            for (int o = 0; o < OO; ++o) {
                const float2 a = s[o];
                l[0][o] += a.x; l[1][o] += a.y;
            }
        }

        const int t   = nt & (TT - 1);
        const int n_i = nt >> 3;
#pragma unroll
        for (int j = 0; j < 2; ++j) {
            const int b = n_i * HWS + 2 * p + j;
#pragma unroll
            for (int h = 0; h < HH; ++h) {
                float m = l[j][h * KK];
#pragma unroll
                for (int k = 1; k < KK; ++k) m = fmaxf(m, l[j][h * KK + k]);
                float e[KK], s = 0.f;
#pragma unroll
                for (int k = 0; k < KK; ++k) {
                    e[k] = __expf(l[j][h * KK + k] - m);
                    s += e[k];
                }
                const float inv = 1.f / s;
                float* dst = g_weights + (((size_t)h * BB + b) * TT + t) * KK;
#pragma unroll
                for (int k = 0; k < KK; ++k) dst[k] = e[k] * inv;
            }
        }
    }
}

// ---------------------------------------------------------------------------
// Kernel 2: causal 5-tap combine.
// grid = (n_i : 16, ct : 64) ; block = 224 threads (196 active = spatial pos).
// Each block: one image, one 8-channel tile (head h = ct/16).
// Per-head weight slice staged in shared, hoisted to 40 regs/thread.
// Channels processed pairwise -> 16 outstanding x loads per thread.
// ---------------------------------------------------------------------------
__global__ void __launch_bounds__(224)
combine_kernel(const float* __restrict__ x, float* __restrict__ out)
{
    __shared__ float wsh[HWS][41];   // 40 weights per sp, pad->41

    const int n_i = blockIdx.x;
    const int ct  = blockIdx.y;           // channel tile of 8
    const int h   = ct >> 4;              // (ct*8)/128

    const float* wsrc = g_weights + ((size_t)h * BB + (size_t)n_i * HWS) * (TT * KK);
    for (int i = threadIdx.x; i < HWS * TT * KK; i += 224)
        wsh[i / 40][i % 40] = wsrc[i];
    __syncthreads();

    const int sp = threadIdx.x;
    if (sp < HWS) {
        float wt[TT][KK];
#pragma unroll
        for (int t = 0; t < TT; ++t)
#pragma unroll
            for (int k = 0; k < KK; ++k)
                wt[t][k] = wsh[sp][t * KK + k];

        const size_t tstride = (size_t)CCH * HWS;           // between nt slices
        const size_t base = ((size_t)n_i * TT * CCH + (size_t)ct * 8) * HWS + sp;

#pragma unroll
        for (int cp = 0; cp < 4; ++cp) {
            const float* xp0 = x + base + (size_t)(2 * cp) * HWS;
            const float* xp1 = xp0 + HWS;
            float a[TT], bv[TT];
#pragma unroll
            for (int t = 0; t < TT; ++t) a[t]  = xp0[(size_t)t * tstride];
#pragma unroll
            for (int t = 0; t < TT; ++t) bv[t] = xp1[(size_t)t * tstride];

            float* op0 = out + base + (size_t)(2 * cp) * HWS;
            float* op1 = op0 + HWS;
#pragma unroll
            for (int t = 0; t < TT; ++t) {
                float s0 = 0.f, s1 = 0.f;
#pragma unroll
                for (int k = 0; k < KK; ++k) {
                    const int src = t + k - 4;               // causal left pad
                    if (src >= 0) {
                        s0 = fmaf(wt[t][k], a[src],  s0);
                        s1 = fmaf(wt[t][k], bv[src], s1);
                    }
                }
                op0[(size_t)t * tstride] = s0;
                op1[(size_t)t * tstride] = s1;
            }
        }
    }
}

// ---------------------------------------------------------------------------
extern "C" void kernel_launch(void* const* d_in, const int* in_sizes, int n_in,
                              void* d_out, int out_size)
{
    const float* x = (const float*)d_in[0];
    const float* W = (const float*)d_in[1];
    float* out = (float*)d_out;

    const int smem1 = 2 * CCH * OO * 4 + 3 * 32 * OO * 8;   // 97280 B
    cudaFuncSetAttribute(weights_kernel,
                         cudaFuncAttributeMaxDynamicSharedMemorySize, smem1);

    weights_kernel<<<NT * 4, 128, smem1>>>(x, W);
    combine_kernel<<<dim3(NN, 64), 224>>>(x, out);
}

// round 4
// speedup vs baseline: 1.6244x; 1.4826x over previous
#include <cuda_runtime.h>
#include <cuda_bf16.h>
#include <cstdint>

// x: (128, 512, 14, 14) fp32 ; W: (20, 512) fp32
// T=8, n=16, B=3136, c=512, H=4, K=5, O=20
#define NT   128
#define CCH  512
#define HWS  196
#define TT   8
#define NN   16
#define HH   4
#define KK   5
#define OO   20
#define BB   3136   // NN * HWS

// scratch: softmax weights laid out [h][b][t][k] (contiguous per-(h,n_i) slice)
__device__ float g_weights[(size_t)HH * BB * TT * KK];

// ---------------------------------------------------------------------------
// Kernel 1: logits (dot over c=512 with 20 W rows) + softmax over K=5 taps.
// SCALAR fp32 FFMA (f32x2 packed FMA measured ~4x slower -> removed).
// Block = 128 threads: warp = c-slice of 128 channels, lane = spatial PAIR
// (float2 load, two scalar accumulator sets). 8-deep x prefetch for MLP.
// Shared: W [c][20] floats (40KB, LDS.128 broadcast) + reduction (15KB)
// => ~56KB -> 3-4 blocks/SM (vs 2 before).
// grid.x = NT*4 (4 blocks of 32 pairs cover 98 pairs per image)
// ---------------------------------------------------------------------------
__global__ void __launch_bounds__(128)
weights_kernel(const float* __restrict__ x, const float* __restrict__ W)
{
    extern __shared__ float smem[];
    float* Wsh = smem;                       // [512][20], 80B rows (16B aligned)
    float* red = smem + CCH * OO;            // [3][32][40]

    const int tid = threadIdx.x;

    // Wsh[c*20+o] = W[o*512+c]  (coalesced read of flat W)
    for (int i = tid; i < OO * CCH; i += 128) {
        const int o = i >> 9;
        const int c = i & (CCH - 1);
        Wsh[c * OO + o] = W[i];
    }
    __syncthreads();

    const int nt    = blockIdx.x >> 2;
    const int pbase = (blockIdx.x & 3) * 32;
    const int cs    = tid >> 5;   // warp = c-slice
    const int lane  = tid & 31;
    const int p     = pbase + lane;          // spatial-pair index
    const bool valid = (p < 98);

    float a0[OO], a1[OO];
#pragma unroll
    for (int o = 0; o < OO; ++o) { a0[o] = 0.f; a1[o] = 0.f; }

    if (valid) {
        const float* xrow = x + ((size_t)nt * CCH + (size_t)cs * 128) * HWS + 2 * p;
        for (int c0 = 0; c0 < 128; c0 += 8) {
            // front-batch 8 independent global float2 loads (MLP=8)
            float2 xv8[8];
#pragma unroll
            for (int i = 0; i < 8; ++i)
                xv8[i] = *reinterpret_cast<const float2*>(xrow + (size_t)(c0 + i) * HWS);
#pragma unroll
            for (int i = 0; i < 8; ++i) {
                const float4* wr = reinterpret_cast<const float4*>(
                                       Wsh + (cs * 128 + c0 + i) * OO);
                const float xa = xv8[i].x, xb = xv8[i].y;
#pragma unroll
                for (int j = 0; j < 5; ++j) {        // 5 x LDS.128 (broadcast)
                    const float4 w4 = wr[j];
                    a0[4*j+0] = fmaf(xa, w4.x, a0[4*j+0]);
                    a1[4*j+0] = fmaf(xb, w4.x, a1[4*j+0]);
                    a0[4*j+1] = fmaf(xa, w4.y, a0[4*j+1]);
                    a1[4*j+1] = fmaf(xb, w4.y, a1[4*j+1]);
                    a0[4*j+2] = fmaf(xa, w4.z, a0[4*j+2]);
                    a1[4*j+2] = fmaf(xb, w4.z, a1[4*j+2]);
                    a0[4*j+3] = fmaf(xa, w4.w, a0[4*j+3]);
                    a1[4*j+3] = fmaf(xb, w4.w, a1[4*j+3]);
                }
            }
        }
    }

    // cross-warp reduction: warps 1..3 dump partials, warp 0 sums
    if (cs > 0) {
        float* dst = red + ((cs - 1) * 32 + lane) * (2 * OO);
#pragma unroll
        for (int o = 0; o < OO; ++o) {
            dst[o]      = a0[o];
            dst[OO + o] = a1[o];
        }
    }
    __syncthreads();

    if (cs == 0 && valid) {
#pragma unroll
        for (int w = 0; w < 3; ++w) {
            const float* s = red + (w * 32 + lane) * (2 * OO);
#pragma unroll
            for (int o = 0; o < OO; ++o) {
                a0[o] += s[o];
                a1[o] += s[OO + o];
            }
        }

        const int t   = nt & (TT - 1);
        const int n_i = nt >> 3;
#pragma unroll
        for (int j = 0; j < 2; ++j) {
            const float* l = j ? a1 : a0;
            const int b = n_i * HWS + 2 * p + j;
#pragma unroll
            for (int h = 0; h < HH; ++h) {
                float m = l[h * KK];
#pragma unroll
                for (int k = 1; k < KK; ++k) m = fmaxf(m, l[h * KK + k]);
                float e[KK], s = 0.f;
#pragma unroll
                for (int k = 0; k < KK; ++k) {
                    e[k] = __expf(l[h * KK + k] - m);
                    s += e[k];
                }
                const float inv = 1.f / s;
                float* dst = g_weights + (((size_t)h * BB + b) * TT + t) * KK;
#pragma unroll
                for (int k = 0; k < KK; ++k) dst[k] = e[k] * inv;
            }
        }
    }
}

// ---------------------------------------------------------------------------
// Kernel 2: causal 5-tap combine.
// grid = (n_i : 16, ct : 32) ; block = 224 threads (196 active = spatial pos).
// Each block: one image, one 16-channel tile (head h = ct/8).
// NO shared staging / NO syncthreads: each thread loads its own 40 weights
// directly (10x LDG.128, L2-resident, reused by 8 blocks per head).
// Channels processed pairwise -> 16 outstanding x loads per thread.
// ---------------------------------------------------------------------------
__global__ void __launch_bounds__(224)
combine_kernel(const float* __restrict__ x, float* __restrict__ out)
{
    const int n_i = blockIdx.x;
    const int ct  = blockIdx.y;           // channel tile of 16
    const int h   = ct >> 3;              // (ct*16)/128

    const int sp = threadIdx.x;
    if (sp >= HWS) return;

    // 40 weights for this (h, b): contiguous, 160B-aligned -> 10 x LDG.128
    float wt[TT * KK];
    {
        const float4* wsrc = reinterpret_cast<const float4*>(
            g_weights + ((size_t)h * BB + (size_t)n_i * HWS + sp) * (TT * KK));
#pragma unroll
        for (int i = 0; i < 10; ++i) {
            const float4 v = wsrc[i];
            wt[4*i+0] = v.x; wt[4*i+1] = v.y; wt[4*i+2] = v.z; wt[4*i+3] = v.w;
        }
    }

    const size_t tstride = (size_t)CCH * HWS;           // between nt slices
    const size_t base = ((size_t)n_i * TT * CCH + (size_t)ct * 16) * HWS + sp;

#pragma unroll
    for (int cp = 0; cp < 8; ++cp) {
        const float* xp0 = x + base + (size_t)(2 * cp) * HWS;
        const float* xp1 = xp0 + HWS;
        float a[TT], bv[TT];
#pragma unroll
        for (int t = 0; t < TT; ++t) a[t]  = xp0[(size_t)t * tstride];
#pragma unroll
        for (int t = 0; t < TT; ++t) bv[t] = xp1[(size_t)t * tstride];

        float* op0 = out + base + (size_t)(2 * cp) * HWS;
        float* op1 = op0 + HWS;
#pragma unroll
        for (int t = 0; t < TT; ++t) {
            float s0 = 0.f, s1 = 0.f;
#pragma unroll
            for (int k = 0; k < KK; ++k) {
                const int src = t + k - 4;               // causal left pad
                if (src >= 0) {
                    s0 = fmaf(wt[t * KK + k], a[src],  s0);
                    s1 = fmaf(wt[t * KK + k], bv[src], s1);
                }
            }
            op0[(size_t)t * tstride] = s0;
            op1[(size_t)t * tstride] = s1;
        }
    }
}

// ---------------------------------------------------------------------------
extern "C" void kernel_launch(void* const* d_in, const int* in_sizes, int n_in,
                              void* d_out, int out_size)
{
    const float* x = (const float*)d_in[0];
    const float* W = (const float*)d_in[1];
    float* out = (float*)d_out;

    const int smem1 = CCH * OO * 4 + 3 * 32 * (2 * OO) * 4;   // 40960+15360=56320
    cudaFuncSetAttribute(weights_kernel,
                         cudaFuncAttributeMaxDynamicSharedMemorySize, smem1);

    weights_kernel<<<NT * 4, 128, smem1>>>(x, W);
    combine_kernel<<<dim3(NN, 32), 224>>>(x, out);
}

// round 5
// speedup vs baseline: 1.7457x; 1.0747x over previous
#include <cuda_runtime.h>
#include <cuda_bf16.h>
#include <cstdint>

// x: (128, 512, 14, 14) fp32 ; W: (20, 512) fp32
// T=8, n=16, B=3136, c=512, H=4, K=5, O=20
#define NT   128
#define CCH  512
#define HWS  196
#define TT   8
#define NN   16
#define HH   4
#define KK   5
#define OO   20
#define BB   3136   // NN * HWS

// scratch: softmax weights laid out [h][b][t][k] (contiguous per-(h,n_i) slice)
__device__ float g_weights[(size_t)HH * BB * TT * KK];

// ---------------------------------------------------------------------------
// Kernel 1: logits (dot over c=512 with 20 W rows) + softmax over K=5 taps.
// Flattened pair index: q = blockIdx.x*32 + lane in [0, 128*98) -> (nt, p).
// ZERO lane padding (W shared across nt). Block = 128 threads, warp = c-slice
// of 128 channels. 8-deep x prefetch. Cross-warp reduction via shared.
// grid.x = 392 (392*32 == 128*98 exactly).
// ---------------------------------------------------------------------------
__global__ void __launch_bounds__(128)
weights_kernel(const float* __restrict__ x, const float* __restrict__ W)
{
    extern __shared__ float smem[];
    float* Wsh = smem;                       // [512][20]
    float* red = smem + CCH * OO;            // [3][32][40]

    const int tid = threadIdx.x;

    // Wsh[c*20+o] = W[o*512+c]  (coalesced read of flat W)
    for (int i = tid; i < OO * CCH; i += 128) {
        const int o = i >> 9;
        const int c = i & (CCH - 1);
        Wsh[c * OO + o] = W[i];
    }
    __syncthreads();

    const int cs   = tid >> 5;    // warp = c-slice
    const int lane = tid & 31;
    const int q    = blockIdx.x * 32 + lane;   // global pair index
    const int nt   = q / 98;
    const int p    = q - nt * 98;              // spatial pair within image

    float a0[OO], a1[OO];
#pragma unroll
    for (int o = 0; o < OO; ++o) { a0[o] = 0.f; a1[o] = 0.f; }

    {
        const float* xrow = x + ((size_t)nt * CCH + (size_t)cs * 128) * HWS + 2 * p;
        for (int c0 = 0; c0 < 128; c0 += 8) {
            // front-batch 8 independent global float2 loads (MLP=8)
            float2 xv8[8];
#pragma unroll
            for (int i = 0; i < 8; ++i)
                xv8[i] = *reinterpret_cast<const float2*>(xrow + (size_t)(c0 + i) * HWS);
#pragma unroll
            for (int i = 0; i < 8; ++i) {
                const float4* wr = reinterpret_cast<const float4*>(
                                       Wsh + (cs * 128 + c0 + i) * OO);
                const float xa = xv8[i].x, xb = xv8[i].y;
#pragma unroll
                for (int j = 0; j < 5; ++j) {        // 5 x LDS.128 (broadcast)
                    const float4 w4 = wr[j];
                    a0[4*j+0] = fmaf(xa, w4.x, a0[4*j+0]);
                    a1[4*j+0] = fmaf(xb, w4.x, a1[4*j+0]);
                    a0[4*j+1] = fmaf(xa, w4.y, a0[4*j+1]);
                    a1[4*j+1] = fmaf(xb, w4.y, a1[4*j+1]);
                    a0[4*j+2] = fmaf(xa, w4.z, a0[4*j+2]);
                    a1[4*j+2] = fmaf(xb, w4.z, a1[4*j+2]);
                    a0[4*j+3] = fmaf(xa, w4.w, a0[4*j+3]);
                    a1[4*j+3] = fmaf(xb, w4.w, a1[4*j+3]);
                }
            }
        }
    }

    // cross-warp reduction: warps 1..3 dump partials, warp 0 sums
    if (cs > 0) {
        float* dst = red + ((cs - 1) * 32 + lane) * (2 * OO);
#pragma unroll
        for (int o = 0; o < OO; ++o) {
            dst[o]      = a0[o];
            dst[OO + o] = a1[o];
        }
    }
    __syncthreads();

    if (cs == 0) {
#pragma unroll
        for (int w = 0; w < 3; ++w) {
            const float* s = red + (w * 32 + lane) * (2 * OO);
#pragma unroll
            for (int o = 0; o < OO; ++o) {
                a0[o] += s[o];
                a1[o] += s[OO + o];
            }
        }

        const int t   = nt & (TT - 1);
        const int n_i = nt >> 3;
#pragma unroll
        for (int j = 0; j < 2; ++j) {
            const float* l = j ? a1 : a0;
            const int b = n_i * HWS + 2 * p + j;
#pragma unroll
            for (int h = 0; h < HH; ++h) {
                float m = l[h * KK];
#pragma unroll
                for (int k = 1; k < KK; ++k) m = fmaxf(m, l[h * KK + k]);
                float e[KK], s = 0.f;
#pragma unroll
                for (int k = 0; k < KK; ++k) {
                    e[k] = __expf(l[h * KK + k] - m);
                    s += e[k];
                }
                const float inv = 1.f / s;
                float* dst = g_weights + (((size_t)h * BB + b) * TT + t) * KK;
#pragma unroll
                for (int k = 0; k < KK; ++k) dst[k] = e[k] * inv;
            }
        }
    }
}

// ---------------------------------------------------------------------------
// Kernel 2: causal 5-tap combine.
// grid = (n_i : 16, ct : 64) ; block = 224 threads (196 active = spatial pos).
// Each block: one image, one 8-channel tile (head h = ct/16).
// No shared staging / no syncthreads: each thread loads its 40 weights
// directly (10x LDG.128, L2-resident). Channels pairwise -> 16 outstanding
// x loads per thread.
// ---------------------------------------------------------------------------
__global__ void __launch_bounds__(224)
combine_kernel(const float* __restrict__ x, float* __restrict__ out)
{
    const int n_i = blockIdx.x;
    const int ct  = blockIdx.y;           // channel tile of 8
    const int h   = ct >> 4;              // (ct*8)/128

    const int sp = threadIdx.x;
    if (sp >= HWS) return;

    // 40 weights for this (h, b): contiguous, 160B-aligned -> 10 x LDG.128
    float wt[TT * KK];
    {
        const float4* wsrc = reinterpret_cast<const float4*>(
            g_weights + ((size_t)h * BB + (size_t)n_i * HWS + sp) * (TT * KK));
#pragma unroll
        for (int i = 0; i < 10; ++i) {
            const float4 v = wsrc[i];
            wt[4*i+0] = v.x; wt[4*i+1] = v.y; wt[4*i+2] = v.z; wt[4*i+3] = v.w;
        }
    }

    const size_t tstride = (size_t)CCH * HWS;           // between nt slices
    const size_t base = ((size_t)n_i * TT * CCH + (size_t)ct * 8) * HWS + sp;

#pragma unroll
    for (int cp = 0; cp < 4; ++cp) {
        const float* xp0 = x + base + (size_t)(2 * cp) * HWS;
        const float* xp1 = xp0 + HWS;
        float a[TT], bv[TT];
#pragma unroll
        for (int t = 0; t < TT; ++t) a[t]  = xp0[(size_t)t * tstride];
#pragma unroll
        for (int t = 0; t < TT; ++t) bv[t] = xp1[(size_t)t * tstride];

        float* op0 = out + base + (size_t)(2 * cp) * HWS;
        float* op1 = op0 + HWS;
#pragma unroll
        for (int t = 0; t < TT; ++t) {
            float s0 = 0.f, s1 = 0.f;
#pragma unroll
            for (int k = 0; k < KK; ++k) {
                const int src = t + k - 4;               // causal left pad
                if (src >= 0) {
                    s0 = fmaf(wt[t * KK + k], a[src],  s0);
                    s1 = fmaf(wt[t * KK + k], bv[src], s1);
                }
            }
            op0[(size_t)t * tstride] = s0;
            op1[(size_t)t * tstride] = s1;
        }
    }
}

// ---------------------------------------------------------------------------
extern "C" void kernel_launch(void* const* d_in, const int* in_sizes, int n_in,
                              void* d_out, int out_size)
{
    const float* x = (const float*)d_in[0];
    const float* W = (const float*)d_in[1];
    float* out = (float*)d_out;

    const int smem1 = CCH * OO * 4 + 3 * 32 * (2 * OO) * 4;   // 40960+15360=56320
    cudaFuncSetAttribute(weights_kernel,
                         cudaFuncAttributeMaxDynamicSharedMemorySize, smem1);

    weights_kernel<<<392, 128, smem1>>>(x, W);
    combine_kernel<<<dim3(NN, 64), 224>>>(x, out);
}

// round 6
// speedup vs baseline: 2.1544x; 1.2341x over previous
#include <cuda_runtime.h>
#include <cuda_bf16.h>
#include <cstdint>

// x: (128, 512, 14, 14) fp32 ; W: (20, 512) fp32
// T=8, n=16, B=3136, c=512, H=4, K=5, O=20
#define NT   128
#define CCH  512
#define HWS  196
#define TT   8
#define NN   16
#define HH   4
#define KK   5
#define OO   20
#define BB   3136   // NN * HWS

// scratch: softmax weights laid out [h][b][t][k]
__device__ float g_weights[(size_t)HH * BB * TT * KK];

// ---------------- kernel 1: TF32 tensor-core logits + softmax ----------------
#define KC      64                    // channels per staged chunk
#define NCHUNK  8                     // 512 / 64
#define APITCH  200                   // smem pitch (floats) for sp dimension
#define ABUF    (KC * APITCH)         // 12800 floats per buffer
#define WPITCH  520                   // W smem pitch (520%32==8 -> conflict-free)
#define WROWS   24                    // pad 20 -> 24 (cols 20..23 garbage, ignored)
#define SMEM1_BYTES ((2 * ABUF + WROWS * WPITCH) * 4)   // 152320

__device__ __forceinline__ uint32_t smem_u32(const void* p) {
    uint32_t a;
    asm("{ .reg .u64 t; cvta.to.shared.u64 t, %1; cvt.u32.u64 %0, t; }"
        : "=r"(a) : "l"(p));
    return a;
}

#define MMA_TF32(d, a0, a1, a2, a3, b0, b1)                                   \
    asm volatile("mma.sync.aligned.m16n8k8.row.col.f32.tf32.tf32.f32 "        \
                 "{%0,%1,%2,%3}, {%4,%5,%6,%7}, {%8,%9}, {%0,%1,%2,%3};"      \
                 : "+f"(d[0]), "+f"(d[1]), "+f"(d[2]), "+f"(d[3])             \
                 : "r"(a0), "r"(a1), "r"(a2), "r"(a3), "r"(b0), "r"(b1))

__global__ void __launch_bounds__(128)
weights_mma_kernel(const float* __restrict__ x, const float* __restrict__ W)
{
    extern __shared__ float smem[];
    float* Abuf = smem;               // [2][KC][APITCH]
    float* Wsh  = smem + 2 * ABUF;    // [24][520] (rows 20..23 never written)

    const int tid = threadIdx.x;
    const int nt  = blockIdx.x;       // image index 0..127
    const int w   = tid >> 5;
    const int l   = tid & 31;
    const int lg  = l >> 2;           // 0..7
    const int lc  = l & 3;            // 0..3

    // stage W rows (raw fp32; mma HW truncates to tf32)
    for (int i = tid; i < OO * CCH; i += 128) {
        const int n = i >> 9, k = i & (CCH - 1);
        Wsh[n * WPITCH + k] = W[i];
    }

    const float* xbase = x + (size_t)nt * CCH * HWS;
    const uint32_t abase_u32 = smem_u32(Abuf);

    // async stage: chunk ck -> buffer b (49 float4 per channel row)
    auto stage = [&](int ck, int b) {
        const float* src = xbase + (size_t)ck * KC * HWS;
        const uint32_t dst0 = abase_u32 + b * (ABUF * 4);
        for (int f = tid; f < (KC * HWS) / 4; f += 128) {
            const int c = f / 49;
            const int s = f - c * 49;
            const uint32_t daddr = dst0 + (c * APITCH + 4 * s) * 4;
            asm volatile("cp.async.cg.shared.global [%0], [%1], 16;"
                         :: "r"(daddr),
                            "l"((const void*)(src + c * HWS + 4 * s))
                         : "memory");
        }
    };

    // per-warp m16 tiles: t = 4j + w, valid if t < 13 (13*16=208 >= 196)
    int spa[4], spb[4];
    bool jvalid[4];
#pragma unroll
    for (int j = 0; j < 4; ++j) {
        const int t = 4 * j + w;
        jvalid[j] = (t < 13);
        const int sp0 = 16 * t + lg;
        spa[j] = min(sp0, APITCH - 1);        // clamp: rows >=196 give garbage,
        spb[j] = min(sp0 + 8, APITCH - 1);    // never stored
    }

    float d[4][3][4];
#pragma unroll
    for (int j = 0; j < 4; ++j)
#pragma unroll
        for (int nf = 0; nf < 3; ++nf)
#pragma unroll
            for (int r = 0; r < 4; ++r) d[j][nf][r] = 0.f;

    stage(0, 0);
    asm volatile("cp.async.commit_group;" ::: "memory");
    stage(1, 1);
    asm volatile("cp.async.commit_group;" ::: "memory");
    asm volatile("cp.async.wait_group 1;" ::: "memory");
    __syncthreads();                           // buf0 ready (and Wsh visible)

    for (int ck = 0; ck < NCHUNK; ++ck) {
        const float* Ab = Abuf + (ck & 1) * ABUF;
#pragma unroll
        for (int k8 = 0; k8 < 8; ++k8) {
            const int kl = k8 * 8;
            const int kg = ck * KC + kl + lc;
            uint32_t bfr[3][2];
#pragma unroll
            for (int nf = 0; nf < 3; ++nf) {
                bfr[nf][0] = __float_as_uint(Wsh[(8 * nf + lg) * WPITCH + kg]);
                bfr[nf][1] = __float_as_uint(Wsh[(8 * nf + lg) * WPITCH + kg + 4]);
            }
            const float* r0 = Ab + (kl + lc) * APITCH;
            const float* r4 = Ab + (kl + lc + 4) * APITCH;
#pragma unroll
            for (int j = 0; j < 4; ++j) {
                if (!jvalid[j]) continue;       // warp-uniform branch
                const uint32_t a0 = __float_as_uint(r0[spa[j]]);
                const uint32_t a1 = __float_as_uint(r0[spb[j]]);
                const uint32_t a2 = __float_as_uint(r4[spa[j]]);
                const uint32_t a3 = __float_as_uint(r4[spb[j]]);
#pragma unroll
                for (int nf = 0; nf < 3; ++nf)
                    MMA_TF32(d[j][nf], a0, a1, a2, a3, bfr[nf][0], bfr[nf][1]);
            }
        }
        __syncthreads();                        // all warps done reading this buf
        if (ck + 2 < NCHUNK) {
            stage(ck + 2, ck & 1);
            asm volatile("cp.async.commit_group;" ::: "memory");
            asm volatile("cp.async.wait_group 1;" ::: "memory");
            __syncthreads();
        } else if (ck + 1 < NCHUNK) {
            asm volatile("cp.async.wait_group 0;" ::: "memory");
            __syncthreads();
        }
    }

    // exchange D through smem (reuse Abuf region): Dx[208][24]
    float* Dx = smem;
#pragma unroll
    for (int j = 0; j < 4; ++j) {
        if (!jvalid[j]) continue;
        const int sp0 = 16 * (4 * j + w) + lg;
#pragma unroll
        for (int nf = 0; nf < 3; ++nf) {
            const int col = nf * 8 + 2 * lc;
            Dx[sp0 * 24 + col]           = d[j][nf][0];
            Dx[sp0 * 24 + col + 1]       = d[j][nf][1];
            Dx[(sp0 + 8) * 24 + col]     = d[j][nf][2];
            Dx[(sp0 + 8) * 24 + col + 1] = d[j][nf][3];
        }
    }
    __syncthreads();

    // per-position softmax over K=5 taps per head, store to g_weights
    const int t_  = nt & (TT - 1);
    const int n_i = nt >> 3;
    for (int sp = tid; sp < HWS; sp += 128) {
        const float* row = Dx + sp * 24;
        const int b = n_i * HWS + sp;
#pragma unroll
        for (int h = 0; h < HH; ++h) {
            float lo[KK];
#pragma unroll
            for (int k = 0; k < KK; ++k) lo[k] = row[h * KK + k];
            float m = lo[0];
#pragma unroll
            for (int k = 1; k < KK; ++k) m = fmaxf(m, lo[k]);
            float e[KK], s = 0.f;
#pragma unroll
            for (int k = 0; k < KK; ++k) { e[k] = __expf(lo[k] - m); s += e[k]; }
            const float inv = 1.f / s;
            float* dst = g_weights + (((size_t)h * BB + b) * TT + t_) * KK;
#pragma unroll
            for (int k = 0; k < KK; ++k) dst[k] = e[k] * inv;
        }
    }
}

// ---------------- kernel 2: causal 5-tap combine (unchanged from R5) --------
__global__ void __launch_bounds__(224)
combine_kernel(const float* __restrict__ x, float* __restrict__ out)
{
    const int n_i = blockIdx.x;
    const int ct  = blockIdx.y;           // channel tile of 8
    const int h   = ct >> 4;

    const int sp = threadIdx.x;
    if (sp >= HWS) return;

    float wt[TT * KK];
    {
        const float4* wsrc = reinterpret_cast<const float4*>(
            g_weights + ((size_t)h * BB + (size_t)n_i * HWS + sp) * (TT * KK));
#pragma unroll
        for (int i = 0; i < 10; ++i) {
            const float4 v = wsrc[i];
            wt[4*i+0] = v.x; wt[4*i+1] = v.y; wt[4*i+2] = v.z; wt[4*i+3] = v.w;
        }
    }

    const size_t tstride = (size_t)CCH * HWS;
    const size_t base = ((size_t)n_i * TT * CCH + (size_t)ct * 8) * HWS + sp;

#pragma unroll
    for (int cp = 0; cp < 4; ++cp) {
        const float* xp0 = x + base + (size_t)(2 * cp) * HWS;
        const float* xp1 = xp0 + HWS;
        float a[TT], bv[TT];
#pragma unroll
        for (int t = 0; t < TT; ++t) a[t]  = xp0[(size_t)t * tstride];
#pragma unroll
        for (int t = 0; t < TT; ++t) bv[t] = xp1[(size_t)t * tstride];

        float* op0 = out + base + (size_t)(2 * cp) * HWS;
        float* op1 = op0 + HWS;
#pragma unroll
        for (int t = 0; t < TT; ++t) {
            float s0 = 0.f, s1 = 0.f;
#pragma unroll
            for (int k = 0; k < KK; ++k) {
                const int src = t + k - 4;
                if (src >= 0) {
                    s0 = fmaf(wt[t * KK + k], a[src],  s0);
                    s1 = fmaf(wt[t * KK + k], bv[src], s1);
                }
            }
            op0[(size_t)t * tstride] = s0;
            op1[(size_t)t * tstride] = s1;
        }
    }
}

// ---------------------------------------------------------------------------
extern "C" void kernel_launch(void* const* d_in, const int* in_sizes, int n_in,
                              void* d_out, int out_size)
{
    const float* x = (const float*)d_in[0];
    const float* W = (const float*)d_in[1];
    float* out = (float*)d_out;

    cudaFuncSetAttribute(weights_mma_kernel,
                         cudaFuncAttributeMaxDynamicSharedMemorySize, SMEM1_BYTES);

    weights_mma_kernel<<<NT, 128, SMEM1_BYTES>>>(x, W);
    combine_kernel<<<dim3(NN, 64), 224>>>(x, out);
}

// round 7
// speedup vs baseline: 2.2602x; 1.0491x over previous
#include <cuda_runtime.h>
#include <cuda_bf16.h>
#include <cstdint>

// x: (128, 512, 14, 14) fp32 ; W: (20, 512) fp32
// T=8, n=16, B=3136, c=512, H=4, K=5, O=20
#define NT   128
#define CCH  512
#define HWS  196
#define TT   8
#define NN   16
#define HH   4
#define KK   5
#define OO   20
#define BB   3136   // NN * HWS

// scratch: softmax weights laid out [h][b][t][k]
__device__ float g_weights[(size_t)HH * BB * TT * KK];

// ---------------- kernel 1: TF32 tensor-core logits + softmax ----------------
// grid = 256: blockIdx.x = nt*2 + half. half0 -> sp [0,96), half1 -> sp [96,196).
// 256 threads (8 warps). Double-buffered cp.async staging of 64-channel chunks.
#define KC      64                    // channels per staged chunk
#define NCHUNK  8                     // 512 / 64
#define APITCH  104                   // smem pitch (104%32==8 -> conflict-free)
#define ABUF    (KC * APITCH)         // 6656 floats per buffer
#define WPITCH  520                   // W smem pitch (520%32==8 -> conflict-free)
#define WROWS   24
#define SMEM1_BYTES ((2 * ABUF + WROWS * WPITCH) * 4)   // 53248+49920=103168

__device__ __forceinline__ uint32_t smem_u32(const void* p) {
    uint32_t a;
    asm("{ .reg .u64 t; cvta.to.shared.u64 t, %1; cvt.u32.u64 %0, t; }"
        : "=r"(a) : "l"(p));
    return a;
}

#define MMA_TF32(d, a0, a1, a2, a3, b0, b1)                                   \
    asm volatile("mma.sync.aligned.m16n8k8.row.col.f32.tf32.tf32.f32 "        \
                 "{%0,%1,%2,%3}, {%4,%5,%6,%7}, {%8,%9}, {%0,%1,%2,%3};"      \
                 : "+f"(d[0]), "+f"(d[1]), "+f"(d[2]), "+f"(d[3])             \
                 : "r"(a0), "r"(a1), "r"(a2), "r"(a3), "r"(b0), "r"(b1))

__global__ void __launch_bounds__(256)
weights_mma_kernel(const float* __restrict__ x, const float* __restrict__ W)
{
    extern __shared__ float smem[];
    float* Abuf = smem;               // [2][KC][APITCH]
    float* Wsh  = smem + 2 * ABUF;    // [24][520] (rows 20..23 never written)

    const int tid  = threadIdx.x;
    const int bid  = blockIdx.x;
    const int nt   = bid >> 1;        // image 0..127
    const int half = bid & 1;
    const int off    = half * 96;     // global sp offset of this half
    const int nsp    = half ? 100 : 96;
    const int nf4    = half ? 25 : 24;   // float4 per channel row
    const int ntiles = half ? 7 : 6;     // m16 tiles (clamped)

    const int w  = tid >> 5;
    const int l  = tid & 31;
    const int lg = l >> 2;            // 0..7
    const int lc = l & 3;             // 0..3

    // stage W rows (raw fp32; mma HW truncates to tf32)
    for (int i = tid; i < OO * CCH; i += 256) {
        const int n = i >> 9, k = i & (CCH - 1);
        Wsh[n * WPITCH + k] = W[i];
    }

    const float* xbase = x + (size_t)nt * CCH * HWS + off;
    const uint32_t abase_u32 = smem_u32(Abuf);
    const int nstage = KC * nf4;      // float4s per chunk

    auto stage = [&](int ck, int b) {
        const float* src = xbase + (size_t)ck * KC * HWS;
        const uint32_t dst0 = abase_u32 + b * (ABUF * 4);
        for (int f = tid; f < nstage; f += 256) {
            const int c = f / nf4;
            const int i = f - c * nf4;
            const uint32_t daddr = dst0 + (c * APITCH + 4 * i) * 4;
            asm volatile("cp.async.cg.shared.global [%0], [%1], 16;"
                         :: "r"(daddr),
                            "l"((const void*)(src + c * HWS + 4 * i))
                         : "memory");
        }
    };

    // one m16 tile per warp: tile index = w, valid if w < ntiles
    const bool tvalid = (w < ntiles);
    const int sp0 = 16 * w + lg;                 // local row within this half
    const int spa = min(sp0, APITCH - 1);        // clamp: rows >= nsp are
    const int spb = min(sp0 + 8, APITCH - 1);    // garbage, never stored

    float d[3][4];
#pragma unroll
    for (int nf = 0; nf < 3; ++nf)
#pragma unroll
        for (int r = 0; r < 4; ++r) d[nf][r] = 0.f;

    stage(0, 0);
    asm volatile("cp.async.commit_group;" ::: "memory");
    stage(1, 1);
    asm volatile("cp.async.commit_group;" ::: "memory");
    asm volatile("cp.async.wait_group 1;" ::: "memory");
    __syncthreads();                           // buf0 ready (and Wsh visible)

    for (int ck = 0; ck < NCHUNK; ++ck) {
        const float* Ab = Abuf + (ck & 1) * ABUF;
#pragma unroll
        for (int k8 = 0; k8 < 8; ++k8) {
            const int kl = k8 * 8;
            const int kg = ck * KC + kl + lc;
            uint32_t bfr[3][2];
#pragma unroll
            for (int nf = 0; nf < 3; ++nf) {
                bfr[nf][0] = __float_as_uint(Wsh[(8 * nf + lg) * WPITCH + kg]);
                bfr[nf][1] = __float_as_uint(Wsh[(8 * nf + lg) * WPITCH + kg + 4]);
            }
            if (tvalid) {
                const float* r0 = Ab + (kl + lc) * APITCH;
                const float* r4 = Ab + (kl + lc + 4) * APITCH;
                const uint32_t a0 = __float_as_uint(r0[spa]);
                const uint32_t a1 = __float_as_uint(r0[spb]);
                const uint32_t a2 = __float_as_uint(r4[spa]);
                const uint32_t a3 = __float_as_uint(r4[spb]);
#pragma unroll
                for (int nf = 0; nf < 3; ++nf)
                    MMA_TF32(d[nf], a0, a1, a2, a3, bfr[nf][0], bfr[nf][1]);
            }
        }
        __syncthreads();                        // all warps done reading buf
        if (ck + 2 < NCHUNK) {
            stage(ck + 2, ck & 1);
            asm volatile("cp.async.commit_group;" ::: "memory");
            asm volatile("cp.async.wait_group 1;" ::: "memory");
            __syncthreads();
        } else if (ck + 1 < NCHUNK) {
            asm volatile("cp.async.wait_group 0;" ::: "memory");
            __syncthreads();
        }
    }

    // exchange D through smem (reuse Abuf region): Dx[112][24]
    float* Dx = smem;
    if (tvalid) {
        const int r = 16 * w + lg;
#pragma unroll
        for (int nf = 0; nf < 3; ++nf) {
            const int col = nf * 8 + 2 * lc;
            Dx[r * 24 + col]           = d[nf][0];
            Dx[r * 24 + col + 1]       = d[nf][1];
            Dx[(r + 8) * 24 + col]     = d[nf][2];
            Dx[(r + 8) * 24 + col + 1] = d[nf][3];
        }
    }
    __syncthreads();

    // per-position softmax over K=5 taps per head, store to g_weights
    const int t_  = nt & (TT - 1);
    const int n_i = nt >> 3;
    for (int s = tid; s < nsp; s += 256) {
        const float* row = Dx + s * 24;
        const int b = n_i * HWS + off + s;
#pragma unroll
        for (int h = 0; h < HH; ++h) {
            float lo[KK];
#pragma unroll
            for (int k = 0; k < KK; ++k) lo[k] = row[h * KK + k];
            float m = lo[0];
#pragma unroll
            for (int k = 1; k < KK; ++k) m = fmaxf(m, lo[k]);
            float e[KK], sum = 0.f;
#pragma unroll
            for (int k = 0; k < KK; ++k) { e[k] = __expf(lo[k] - m); sum += e[k]; }
            const float inv = 1.f / sum;
            float* dst = g_weights + (((size_t)h * BB + b) * TT + t_) * KK;
#pragma unroll
            for (int k = 0; k < KK; ++k) dst[k] = e[k] * inv;
        }
    }
}

// ---------------- kernel 2: causal 5-tap combine (unchanged) ----------------
__global__ void __launch_bounds__(224)
combine_kernel(const float* __restrict__ x, float* __restrict__ out)
{
    const int n_i = blockIdx.x;
    const int ct  = blockIdx.y;           // channel tile of 8
    const int h   = ct >> 4;

    const int sp = threadIdx.x;
    if (sp >= HWS) return;

    float wt[TT * KK];
    {
        const float4* wsrc = reinterpret_cast<const float4*>(
            g_weights + ((size_t)h * BB + (size_t)n_i * HWS + sp) * (TT * KK));
#pragma unroll
        for (int i = 0; i < 10; ++i) {
            const float4 v = wsrc[i];
            wt[4*i+0] = v.x; wt[4*i+1] = v.y; wt[4*i+2] = v.z; wt[4*i+3] = v.w;
        }
    }

    const size_t tstride = (size_t)CCH * HWS;
    const size_t base = ((size_t)n_i * TT * CCH + (size_t)ct * 8) * HWS + sp;

#pragma unroll
    for (int cp = 0; cp < 4; ++cp) {
        const float* xp0 = x + base + (size_t)(2 * cp) * HWS;
        const float* xp1 = xp0 + HWS;
        float a[TT], bv[TT];
#pragma unroll
        for (int t = 0; t < TT; ++t) a[t]  = xp0[(size_t)t * tstride];
#pragma unroll
        for (int t = 0; t < TT; ++t) bv[t] = xp1[(size_t)t * tstride];

        float* op0 = out + base + (size_t)(2 * cp) * HWS;
        float* op1 = op0 + HWS;
#pragma unroll
        for (int t = 0; t < TT; ++t) {
            float s0 = 0.f, s1 = 0.f;
#pragma unroll
            for (int k = 0; k < KK; ++k) {
                const int src = t + k - 4;
                if (src >= 0) {
                    s0 = fmaf(wt[t * KK + k], a[src],  s0);
                    s1 = fmaf(wt[t * KK + k], bv[src], s1);
                }
            }
            op0[(size_t)t * tstride] = s0;
            op1[(size_t)t * tstride] = s1;
        }
    }
}

// ---------------------------------------------------------------------------
extern "C" void kernel_launch(void* const* d_in, const int* in_sizes, int n_in,
                              void* d_out, int out_size)
{
    const float* x = (const float*)d_in[0];
    const float* W = (const float*)d_in[1];
    float* out = (float*)d_out;

    cudaFuncSetAttribute(weights_mma_kernel,
                         cudaFuncAttributeMaxDynamicSharedMemorySize, SMEM1_BYTES);

    weights_mma_kernel<<<2 * NT, 256, SMEM1_BYTES>>>(x, W);
    combine_kernel<<<dim3(NN, 64), 224>>>(x, out);
}

// round 9
// speedup vs baseline: 2.4644x; 1.0904x over previous
#include <cuda_runtime.h>
#include <cuda_bf16.h>
#include <cstdint>

// x: (128, 512, 14, 14) fp32 ; W: (20, 512) fp32
// T=8, n=16, B=3136, c=512, H=4, K=5, O=20
#define NT   128
#define CCH  512
#define HWS  196
#define TT   8
#define NN   16
#define HH   4
#define KK   5
#define OO   20
#define BB   3136   // NN * HWS

// scratch: softmax weights, layout [h][t][k][B]  (coalesced at both ends)
__device__ float g_weights[(size_t)HH * TT * KK * BB];
#define GW_IDX(h, t, k, b) ((((size_t)(h) * TT + (t)) * KK + (k)) * BB + (b))

// ---------------- kernel 1: TF32 tensor-core logits + softmax ----------------
// grid = 256: blockIdx.x = nt*2 + half. half0 -> sp [0,96), half1 -> sp [96,196).
// 256 threads (8 warps). 4-deep cp.async pipeline, 32-channel chunks.
#define KC      32                    // channels per staged chunk
#define NCHUNK  16                    // 512 / 32
#define NBUF    4
#define APITCH  104                   // smem pitch (104%32==8 -> conflict-free)
#define ABUF    (KC * APITCH)         // 3328 floats per buffer
#define WPITCH  520                   // W smem pitch (conflict-free)
#define WROWS   24
#define SMEM1_BYTES ((NBUF * ABUF + WROWS * WPITCH) * 4)   // 53248+49920=103168

__device__ __forceinline__ uint32_t smem_u32(const void* p) {
    uint32_t a;
    asm("{ .reg .u64 t; cvta.to.shared.u64 t, %1; cvt.u32.u64 %0, t; }"
        : "=r"(a) : "l"(p));
    return a;
}

#define MMA_TF32(d, a0, a1, a2, a3, b0, b1)                                   \
    asm volatile("mma.sync.aligned.m16n8k8.row.col.f32.tf32.tf32.f32 "        \
                 "{%0,%1,%2,%3}, {%4,%5,%6,%7}, {%8,%9}, {%0,%1,%2,%3};"      \
                 : "+f"(d[0]), "+f"(d[1]), "+f"(d[2]), "+f"(d[3])             \
                 : "r"(a0), "r"(a1), "r"(a2), "r"(a3), "r"(b0), "r"(b1))

__global__ void __launch_bounds__(256)
weights_mma_kernel(const float* __restrict__ x, const float* __restrict__ W)
{
    extern __shared__ float smem[];
    float* Abuf = smem;                    // [4][KC][APITCH]
    float* Wsh  = smem + NBUF * ABUF;      // [24][520] (rows 20..23 unused)

    const int tid  = threadIdx.x;
    const int bid  = blockIdx.x;
    const int nt   = bid >> 1;             // image 0..127
    const int half = bid & 1;
    const int off  = half * 96;            // global sp offset of this half
    const int nsp  = half ? 100 : 96;
    const int nf4  = half ? 25 : 24;       // float4 per channel row
    const int ntiles = half ? 7 : 6;       // m16 tiles

    const int w  = tid >> 5;
    const int l  = tid & 31;
    const int lg = l >> 2;                 // 0..7
    const int lc = l & 3;                  // 0..3

    // stage W rows (raw fp32; mma HW truncates to tf32)
    for (int i = tid; i < OO * CCH; i += 256) {
        const int n = i >> 9, k = i & (CCH - 1);
        Wsh[n * WPITCH + k] = W[i];
    }

    const float* xbase = x + (size_t)nt * CCH * HWS + off;
    const uint32_t abase_u32 = smem_u32(Abuf);
    const int nstage = KC * nf4;           // float4s per chunk

    auto stage = [&](int ck) {
        const float* src = xbase + (size_t)ck * KC * HWS;
        const uint32_t dst0 = abase_u32 + (ck & (NBUF - 1)) * (ABUF * 4);
        for (int f = tid; f < nstage; f += 256) {
            const int c = f / nf4;
            const int i = f - c * nf4;
            const uint32_t daddr = dst0 + (c * APITCH + 4 * i) * 4;
            asm volatile("cp.async.cg.shared.global [%0], [%1], 16;"
                         :: "r"(daddr),
                            "l"((const void*)(src + c * HWS + 4 * i))
                         : "memory");
        }
        asm volatile("cp.async.commit_group;" ::: "memory");
    };

    // one m16 tile per warp
    const bool tvalid = (w < ntiles);
    const int sp0 = 16 * w + lg;
    const int spa = min(sp0, APITCH - 1);       // clamped rows never stored
    const int spb = min(sp0 + 8, APITCH - 1);

    float d[3][4];
#pragma unroll
    for (int nf = 0; nf < 3; ++nf)
#pragma unroll
        for (int r = 0; r < 4; ++r) d[nf][r] = 0.f;

    stage(0); stage(1); stage(2);          // 3 chunks in flight

    for (int ck = 0; ck < NCHUNK; ++ck) {
        // TAIL-AWARE wait: guarantee chunk ck's group has completed.
        // Groups are committed in order; after iteration ck-1 the last
        // committed group is min(ck+2, NCHUNK-1). Pending allowed =
        // (last committed) - ck.
        if (ck < NCHUNK - 2) {
            asm volatile("cp.async.wait_group 2;" ::: "memory");
        } else if (ck == NCHUNK - 2) {
            asm volatile("cp.async.wait_group 1;" ::: "memory");
        } else {
            asm volatile("cp.async.wait_group 0;" ::: "memory");
        }
        __syncthreads();

        const float* Ab = Abuf + (ck & (NBUF - 1)) * ABUF;
#pragma unroll
        for (int k8 = 0; k8 < KC / 8; ++k8) {
            const int kl = k8 * 8;
            const int kg = ck * KC + kl + lc;
            uint32_t bfr[3][2];
#pragma unroll
            for (int nf = 0; nf < 3; ++nf) {
                bfr[nf][0] = __float_as_uint(Wsh[(8 * nf + lg) * WPITCH + kg]);
                bfr[nf][1] = __float_as_uint(Wsh[(8 * nf + lg) * WPITCH + kg + 4]);
            }
            if (tvalid) {
                const float* r0 = Ab + (kl + lc) * APITCH;
                const float* r4 = Ab + (kl + lc + 4) * APITCH;
                const uint32_t a0 = __float_as_uint(r0[spa]);
                const uint32_t a1 = __float_as_uint(r0[spb]);
                const uint32_t a2 = __float_as_uint(r4[spa]);
                const uint32_t a3 = __float_as_uint(r4[spb]);
#pragma unroll
                for (int nf = 0; nf < 3; ++nf)
                    MMA_TF32(d[nf], a0, a1, a2, a3, bfr[nf][0], bfr[nf][1]);
            }
        }
        __syncthreads();                        // buf consumed, safe to restage
        if (ck + 3 < NCHUNK) stage(ck + 3);
    }

    // exchange D through smem (reuse Abuf region): Dx[112][24]
    float* Dx = smem;
    if (tvalid) {
        const int r = 16 * w + lg;
#pragma unroll
        for (int nf = 0; nf < 3; ++nf) {
            const int col = nf * 8 + 2 * lc;
            Dx[r * 24 + col]           = d[nf][0];
            Dx[r * 24 + col + 1]       = d[nf][1];
            Dx[(r + 8) * 24 + col]     = d[nf][2];
            Dx[(r + 8) * 24 + col + 1] = d[nf][3];
        }
    }
    __syncthreads();

    // per-position softmax; stores coalesced in [h][t][k][B] layout
    const int t_  = nt & (TT - 1);
    const int n_i = nt >> 3;
    for (int s = tid; s < nsp; s += 256) {
        const float* row = Dx + s * 24;
        const int b = n_i * HWS + off + s;
#pragma unroll
        for (int h = 0; h < HH; ++h) {
            float lo[KK];
#pragma unroll
            for (int k = 0; k < KK; ++k) lo[k] = row[h * KK + k];
            float m = lo[0];
#pragma unroll
            for (int k = 1; k < KK; ++k) m = fmaxf(m, lo[k]);
            float e[KK], sum = 0.f;
#pragma unroll
            for (int k = 0; k < KK; ++k) { e[k] = __expf(lo[k] - m); sum += e[k]; }
            const float inv = 1.f / sum;
#pragma unroll
            for (int k = 0; k < KK; ++k)
                g_weights[GW_IDX(h, t_, k, b)] = e[k] * inv;
        }
    }
}

// ---------------- kernel 2: causal 5-tap combine ----------------------------
// grid = (n_i : 16, ct : 64) ; block = 224 threads (196 active = spatial pos).
// Weights read coalesced: 40 independent LDG.32 per thread (L2-resident).
__global__ void __launch_bounds__(224)
combine_kernel(const float* __restrict__ x, float* __restrict__ out)
{
    const int n_i = blockIdx.x;
    const int ct  = blockIdx.y;           // channel tile of 8
    const int h   = ct >> 4;

    const int sp = threadIdx.x;
    if (sp >= HWS) return;

    const int b = n_i * HWS + sp;
    float wt[TT * KK];
#pragma unroll
    for (int t = 0; t < TT; ++t)
#pragma unroll
        for (int k = 0; k < KK; ++k)
            wt[t * KK + k] = g_weights[GW_IDX(h, t, k, b)];

    const size_t tstride = (size_t)CCH * HWS;
    const size_t base = ((size_t)n_i * TT * CCH + (size_t)ct * 8) * HWS + sp;

#pragma unroll
    for (int cp = 0; cp < 4; ++cp) {
        const float* xp0 = x + base + (size_t)(2 * cp) * HWS;
        const float* xp1 = xp0 + HWS;
        float a[TT], bv[TT];
#pragma unroll
        for (int t = 0; t < TT; ++t) a[t]  = xp0[(size_t)t * tstride];
#pragma unroll
        for (int t = 0; t < TT; ++t) bv[t] = xp1[(size_t)t * tstride];

        float* op0 = out + base + (size_t)(2 * cp) * HWS;
        float* op1 = op0 + HWS;
#pragma unroll
        for (int t = 0; t < TT; ++t) {
            float s0 = 0.f, s1 = 0.f;
#pragma unroll
            for (int k = 0; k < KK; ++k) {
                const int src = t + k - 4;
                if (src >= 0) {
                    s0 = fmaf(wt[t * KK + k], a[src],  s0);
                    s1 = fmaf(wt[t * KK + k], bv[src], s1);
                }
            }
            op0[(size_t)t * tstride] = s0;
            op1[(size_t)t * tstride] = s1;
        }
    }
}

// ---------------------------------------------------------------------------
extern "C" void kernel_launch(void* const* d_in, const int* in_sizes, int n_in,
                              void* d_out, int out_size)
{
    const float* x = (const float*)d_in[0];
    const float* W = (const float*)d_in[1];
    float* out = (float*)d_out;

    cudaFuncSetAttribute(weights_mma_kernel,
                         cudaFuncAttributeMaxDynamicSharedMemorySize, SMEM1_BYTES);

    weights_mma_kernel<<<2 * NT, 256, SMEM1_BYTES>>>(x, W);
    combine_kernel<<<dim3(NN, 64), 224>>>(x, out);
}